// round 8
// baseline (speedup 1.0000x reference)
#include <cuda_runtime.h>
#include <cstdint>

#define N 4096
#define D 256
#define C 1000
#define BM 128
#define NT (N / BM)                 // 32
#define NTILES (NT * (NT + 1) / 2)  // 528
#define BK 16
#define STAGES 4
#define PITCH 20                    // floats per smem tile row (16 slots + 4 pad)
#define TILE_F (BM * PITCH)         // 2560 floats per operand tile

// Shared memory layout (floats):
#define OFF_SDP   0                           // 64*256 = 16384 (parked dP)
#define OFF_TILES 16384                       // STAGES x {A,B} = 4*2*2560 = 20480
#define OFF_SQ    (OFF_TILES + STAGES * 2 * TILE_F)
#define OFF_SRED  (OFF_SQ + 512)
#define SMEM_FLOATS (OFF_SRED + 8)
#define SMEM_BYTES (SMEM_FLOATS * 4)          // 149,536 B

__device__ double g_acc[4];
__device__ float  g_sqn[6][N];
// tf32-truncated, k-permuted copies of the 6 feature matrices (24 MB).
__device__ float  g_tf[6][N * D];

// ---------------------------------------------------------------------------
__device__ __forceinline__ uint32_t smem_u32(const void* p) {
    uint32_t a;
    asm("{ .reg .u64 t; cvta.to.shared.u64 t, %1; cvt.u32.u64 %0, t; }" : "=r"(a) : "l"(p));
    return a;
}
__device__ __forceinline__ uint32_t to_tf32(float f) {
    uint32_t u;
    asm("cvt.rna.tf32.f32 %0, %1;" : "=r"(u) : "f"(f));
    return u;
}
__device__ __forceinline__ void mma_tf32(float* d, uint32_t a0, uint32_t a1,
                                         uint32_t a2, uint32_t a3,
                                         uint32_t b0, uint32_t b1) {
    asm volatile(
        "mma.sync.aligned.m16n8k8.row.col.f32.tf32.tf32.f32 "
        "{%0,%1,%2,%3}, {%4,%5,%6,%7}, {%8,%9}, {%0,%1,%2,%3};"
        : "+f"(d[0]), "+f"(d[1]), "+f"(d[2]), "+f"(d[3])
        : "r"(a0), "r"(a1), "r"(a2), "r"(a3), "r"(b0), "r"(b1));
}
#define CP_ASYNC16(dst, src) \
    asm volatile("cp.async.cg.shared.global [%0], [%1], 16;" :: "r"(dst), "l"(src) : "memory")
#define CP_COMMIT() asm volatile("cp.async.commit_group;" ::: "memory")
#define CP_WAIT2()  asm volatile("cp.async.wait_group 2;" ::: "memory")

// ---------------------------------------------------------------------------
__global__ void zero_kernel() {
    if (threadIdx.x < 4) g_acc[threadIdx.x] = 0.0;
}

// One 8-group of k per thread: truncate to tf32 and permute k so that the
// mma fragment pair (k=q, k=q+4) is contiguous in memory:
//   out[0]=k0 out[1]=k4 out[2]=k1 out[3]=k5 out[4]=k2 out[5]=k6 out[6]=k3 out[7]=k7
__global__ void prep_kernel(const float* __restrict__ f0, const float* __restrict__ f1,
                            const float* __restrict__ f2, const float* __restrict__ f3,
                            const float* __restrict__ f4, const float* __restrict__ f5) {
    int idx = blockIdx.x * blockDim.x + threadIdx.x;   // 0 .. 6*N*D/8-1
    if (idx >= 6 * N * D / 8) return;
    int m   = idx >> 17;                 // / (N*D/8) = /131072
    int rem = idx & 131071;
    const float* src;
    switch (m) {
        case 0: src = f0; break; case 1: src = f1; break; case 2: src = f2; break;
        case 3: src = f3; break; case 4: src = f4; break; default: src = f5; break;
    }
    float4 lo = ((const float4*)src)[rem * 2];
    float4 hi = ((const float4*)src)[rem * 2 + 1];
    uint4 o0, o1;
    o0.x = to_tf32(lo.x); o0.y = to_tf32(hi.x); o0.z = to_tf32(lo.y); o0.w = to_tf32(hi.y);
    o1.x = to_tf32(lo.z); o1.y = to_tf32(hi.z); o1.z = to_tf32(lo.w); o1.w = to_tf32(hi.w);
    ((uint4*)g_tf[m])[rem * 2]     = o0;
    ((uint4*)g_tf[m])[rem * 2 + 1] = o1;
}

// Row squared norms (fp32, full precision), one warp per row.
__global__ void sqn_kernel(const float* __restrict__ f0, const float* __restrict__ f1,
                           const float* __restrict__ f2, const float* __restrict__ f3,
                           const float* __restrict__ f4, const float* __restrict__ f5) {
    int gw   = (blockIdx.x * blockDim.x + threadIdx.x) >> 5;
    int lane = threadIdx.x & 31;
    if (gw >= 6 * N) return;
    int f = gw >> 12;
    int row = gw & (N - 1);
    const float* src;
    switch (f) {
        case 0: src = f0; break; case 1: src = f1; break; case 2: src = f2; break;
        case 3: src = f3; break; case 4: src = f4; break; default: src = f5; break;
    }
    const float4* p = (const float4*)(src + (size_t)row * D);
    float s = 0.f;
#pragma unroll
    for (int i = 0; i < 2; i++) {
        float4 v = p[lane + 32 * i];
        s += v.x * v.x + v.y * v.y + v.z * v.z + v.w * v.w;
    }
#pragma unroll
    for (int o = 16; o; o >>= 1) s += __shfl_xor_sync(0xffffffffu, s, o);
    if (lane == 0) g_sqn[f][row] = s;
}

__global__ void label_kernel(const float* __restrict__ pred,
                             const float* __restrict__ target) {
    __shared__ float sred[256];
    const int n4 = N * C / 4;
    float s = 0.f;
    for (int i = blockIdx.x * blockDim.x + threadIdx.x; i < n4;
         i += gridDim.x * blockDim.x) {
        float4 a = ((const float4*)pred)[i];
        float4 b = ((const float4*)target)[i];
        float dx = a.x - b.x, dy = a.y - b.y, dz = a.z - b.z, dw = a.w - b.w;
        s += dx * dx + dy * dy + dz * dz + dw * dw;
    }
    sred[threadIdx.x] = s;
    __syncthreads();
    for (int o = 128; o; o >>= 1) {
        if (threadIdx.x < o) sred[threadIdx.x] += sred[threadIdx.x + o];
        __syncthreads();
    }
    if (threadIdx.x == 0) atomicAdd(&g_acc[0], (double)sred[0]);
}

// ---------------------------------------------------------------------------
// Tensor-core fused pairwise tile kernel, cp.async pipelined (4 stages).
// Data comes pre-truncated + k-permuted from g_tf, so the hot loop has zero
// conversions and zero register staging.
__global__ void __launch_bounds__(256)
pair_kernel() {
    extern __shared__ float sm[];
    const uint32_t sb_tiles = smem_u32(sm + OFF_TILES);

    const int f = blockIdx.y;
    int bi = 0, rem = blockIdx.x;
    while (rem >= NT - bi) { rem -= NT - bi; bi++; }
    const int bj = bi + rem;

    const int tid  = threadIdx.x;
    const int wid  = tid >> 5, lane = tid & 31;
    const int wi   = wid & 3;        // row warp group
    const int wj   = wid >> 2;       // col warp group
    const int tg   = lane >> 2;
    const int q    = lane & 3;
    const int rowI = bi * BM, rowJ = bj * BM;

    if (tid < 128) {
        sm[OFF_SQ +       tid] = g_sqn[f][rowI + tid];
        sm[OFF_SQ + 128 + tid] = g_sqn[f][rowJ + tid];
        sm[OFF_SQ + 256 + tid] = g_sqn[3 + f][rowI + tid];
        sm[OFF_SQ + 384 + tid] = g_sqn[3 + f][rowJ + tid];
    }

    // Copy slots: thread covers rows rA and rA+64 of each tile, 16B seg qf.
    const int rA = tid >> 2;
    const int qf = tid & 3;
    const uint32_t dOff0 = (uint32_t)(rA * PITCH + qf * 4) * 4;
    const uint32_t dOff1 = (uint32_t)((rA + 64) * PITCH + qf * 4) * 4;

    float s_total = 0.f;

#pragma unroll 1
    for (int phase = 0; phase < 2; ++phase) {
        const float* Ag = g_tf[phase ? 3 + f : f] + (size_t)rowI * D;
        const float* Bg = g_tf[phase ? 3 + f : f] + (size_t)rowJ * D;

        float acc[2][8][4];
#pragma unroll
        for (int mt = 0; mt < 2; mt++)
#pragma unroll
            for (int nt = 0; nt < 8; nt++)
#pragma unroll
                for (int e = 0; e < 4; e++) acc[mt][nt][e] = 0.f;

        // Prologue: issue chunks 0..2.
#pragma unroll
        for (int p = 0; p < STAGES - 1; p++) {
            const uint32_t dA = sb_tiles + (uint32_t)p * (2 * TILE_F * 4);
            const uint32_t dB = dA + TILE_F * 4;
            const float* gA = Ag + p * BK + qf * 4;
            const float* gB = Bg + p * BK + qf * 4;
            CP_ASYNC16(dA + dOff0, gA + (size_t)rA * D);
            CP_ASYNC16(dA + dOff1, gA + (size_t)(rA + 64) * D);
            CP_ASYNC16(dB + dOff0, gB + (size_t)rA * D);
            CP_ASYNC16(dB + dOff1, gB + (size_t)(rA + 64) * D);
            CP_COMMIT();
        }

#pragma unroll 1
        for (int c = 0; c < D / BK; c++) {
            CP_WAIT2();            // chunk c complete
            __syncthreads();

            const float* sA = sm + OFF_TILES + (c & 3) * 2 * TILE_F;
            const float* sB = sA + TILE_F;
#pragma unroll
            for (int g = 0; g < 2; g++) {
                uint32_t a0[2], a1[2], a2[2], a3[2];
#pragma unroll
                for (int mt = 0; mt < 2; mt++) {
                    float2 lo = *(const float2*)&sA[(wi * 32 + mt * 16 + tg) * PITCH + g * 8 + 2 * q];
                    float2 hi = *(const float2*)&sA[(wi * 32 + mt * 16 + tg + 8) * PITCH + g * 8 + 2 * q];
                    a0[mt] = __float_as_uint(lo.x);
                    a2[mt] = __float_as_uint(lo.y);
                    a1[mt] = __float_as_uint(hi.x);
                    a3[mt] = __float_as_uint(hi.y);
                }
#pragma unroll
                for (int nt = 0; nt < 8; nt++) {
                    float2 fb = *(const float2*)&sB[(wj * 64 + nt * 8 + tg) * PITCH + g * 8 + 2 * q];
                    uint32_t b0 = __float_as_uint(fb.x), b1 = __float_as_uint(fb.y);
                    mma_tf32(acc[0][nt], a0[0], a1[0], a2[0], a3[0], b0, b1);
                    mma_tf32(acc[1][nt], a0[1], a1[1], a2[1], a3[1], b0, b1);
                }
            }

            // Issue chunk c+3 into buffer (c+3)&3 (safe: that buffer's compute
            // finished before this iteration's __syncthreads).
            if (c + STAGES - 1 < D / BK) {
                const int x = c + STAGES - 1;
                const uint32_t dA = sb_tiles + (uint32_t)(x & 3) * (2 * TILE_F * 4);
                const uint32_t dB = dA + TILE_F * 4;
                const float* gA = Ag + x * BK + qf * 4;
                const float* gB = Bg + x * BK + qf * 4;
                CP_ASYNC16(dA + dOff0, gA + (size_t)rA * D);
                CP_ASYNC16(dA + dOff1, gA + (size_t)(rA + 64) * D);
                CP_ASYNC16(dB + dOff0, gB + (size_t)rA * D);
                CP_ASYNC16(dB + dOff1, gB + (size_t)(rA + 64) * D);
                CP_COMMIT();
            }
        }

        // Epilogue: distances; park dP (phase 0) or accumulate (phase 1).
        const float* sqi = sm + OFF_SQ + phase * 256;
        const float* sqj = sqi + 128;
#pragma unroll
        for (int mt = 0; mt < 2; mt++)
#pragma unroll
            for (int nt = 0; nt < 8; nt++)
#pragma unroll
                for (int e = 0; e < 4; e++) {
                    int lr = wi * 32 + mt * 16 + tg + ((e >> 1) << 3);
                    int lc = wj * 64 + nt * 8 + 2 * q + (e & 1);
                    float sq = sqi[lr] + sqj[lc] - 2.f * acc[mt][nt][e];
                    float dd = sq > 0.f ? sq * rsqrtf(sq) : 0.f;
                    int slot = OFF_SDP + ((mt * 8 + nt) * 4 + e) * 256 + tid;
                    if (phase == 0) {
                        sm[slot] = dd;
                    } else {
                        float d = sm[slot] - dd;
                        s_total += d * d;
                    }
                }
    }

    s_total *= (bi == bj) ? 1.f : 2.f;
#pragma unroll
    for (int o = 16; o; o >>= 1) s_total += __shfl_xor_sync(0xffffffffu, s_total, o);
    if (lane == 0) sm[OFF_SRED + wid] = s_total;
    __syncthreads();
    if (tid == 0) {
        double tot = 0.0;
#pragma unroll
        for (int w = 0; w < 8; w++) tot += (double)sm[OFF_SRED + w];
        atomicAdd(&g_acc[1 + f], tot);
    }
}

// ---------------------------------------------------------------------------
__global__ void final_kernel(float* __restrict__ out) {
    double label = g_acc[0] / ((double)N * (double)C);
    double feat  = (g_acc[1] + g_acc[2] + g_acc[3]) / ((double)N * (double)N);
    out[0] = (float)((1.0 - 0.8) * label + 0.8 * feat / 3.0);
}

// ---------------------------------------------------------------------------
extern "C" void kernel_launch(void* const* d_in, const int* in_sizes, int n_in,
                              void* d_out, int out_size) {
    const float* pred   = (const float*)d_in[0];
    const float* target = (const float*)d_in[1];
    const float* pf0 = (const float*)d_in[2];
    const float* pf1 = (const float*)d_in[3];
    const float* pf2 = (const float*)d_in[4];
    const float* tf0 = (const float*)d_in[5];
    const float* tf1 = (const float*)d_in[6];
    const float* tf2 = (const float*)d_in[7];
    float* out = (float*)d_out;

    static int configured = 0;
    if (!configured) {
        cudaFuncSetAttribute(pair_kernel,
                             cudaFuncAttributeMaxDynamicSharedMemorySize, SMEM_BYTES);
        configured = 1;
    }

    zero_kernel<<<1, 32>>>();
    prep_kernel<<<(6 * N * D / 8 + 255) / 256, 256>>>(pf0, pf1, pf2, tf0, tf1, tf2);
    sqn_kernel<<<(6 * N) / 8, 256>>>(pf0, pf1, pf2, tf0, tf1, tf2);
    label_kernel<<<512, 256>>>(pred, target);

    dim3 grid(NTILES, 3);
    pair_kernel<<<grid, 256, SMEM_BYTES>>>();

    final_kernel<<<1, 1>>>(out);
}